// round 11
// baseline (speedup 1.0000x reference)
#include <cuda_runtime.h>
#include <math.h>

typedef unsigned long long ull;
constexpr int S_ = 500;

// ---------------- device scratch ----------------
__device__ float g_at2[1001 * 104];              // duplicated attn pairs [q][2m..2m+1]
__device__ float g_c1[1001 * 100];
__device__ float g_ea[(size_t)4004 * 400];
__device__ float g_w2e[56 * 100];                // [W2(50); Wo@W2(4); colmean W2(1); 0]
__device__ float g_b2e[56];
__device__ float g_h[(size_t)512 * 500 * 200];   // read vectors [b][t][200]

// ---------------- f32x2 helpers ----------------
#define FMA2(d, a, b, c) \
    asm("fma.rn.f32x2 %0, %1, %2, %3;" : "=l"(d) : "l"(a), "l"(b), "l"(c))
__device__ __forceinline__ ull PK(float x, float y) {
    ull u;
    asm("mov.b64 %0, {%1, %2};" : "=l"(u) : "r"(__float_as_uint(x)), "r"(__float_as_uint(y)));
    return u;
}
__device__ __forceinline__ float HADD(ull u) {
    unsigned lo, hi;
    asm("mov.b64 {%0, %1}, %2;" : "=r"(lo), "=r"(hi) : "l"(u));
    return __uint_as_float(lo) + __uint_as_float(hi);
}
__device__ __forceinline__ void cp16(float* dst, const float* src) {
    unsigned d = (unsigned)__cvta_generic_to_shared(dst);
    asm volatile("cp.async.ca.shared.global [%0], [%1], 16;\n" :: "r"(d), "l"(src));
}

// ================= prepBF: attn(+tk inline) | c1 | fold =================
__global__ void prepBF(const float* __restrict__ qet, const float* __restrict__ Wq,
                       const float* __restrict__ bq,
                       const float* __restrict__ km, const float* __restrict__ Wk,
                       const float* __restrict__ bk,
                       const float* __restrict__ W1, const float* __restrict__ b1,
                       const float* __restrict__ W2, const float* __restrict__ b2,
                       const float* __restrict__ Wo, const float* __restrict__ bo) {
    __shared__ float stk[2500], qe[50], qu[50], lg[50], red[2];
    int b = blockIdx.x, tid = threadIdx.x;
    if (b < 1001) {
        int q = b;
        for (int i = tid; i < 2500; i += 256) {
            int m = i / 50, k = i % 50;
            float a = bk[m];
            for (int l = 0; l < 50; l++) a = fmaf(km[l * 50 + k], Wk[m * 50 + l], a);
            stk[i] = a;
        }
        if (tid < 50) qe[tid] = qet[q * 50 + tid];
        __syncthreads();
        if (tid < 50) {
            float a = bq[tid];
            for (int l = 0; l < 50; l++) a = fmaf(Wq[tid * 50 + l], qe[l], a);
            qu[tid] = tanhf(a);
        }
        __syncthreads();
        if (tid < 50) {
            float a = 0.f;
            for (int k = 0; k < 50; k++) a = fmaf(stk[tid * 50 + k], qu[k], a);
            lg[tid] = a;
        }
        __syncthreads();
        if (tid == 0) {
            float mx = -1e30f;
            for (int m = 0; m < 50; m++) mx = fmaxf(mx, lg[m]);
            float s = 0.f;
            for (int m = 0; m < 50; m++) s += expf(lg[m] - mx);
            red[0] = mx; red[1] = 1.f / s;
        }
        __syncthreads();
        if (tid < 52) {
            float v = (tid < 50) ? expf(lg[tid] - red[0]) * red[1] : 0.f;
            g_at2[q * 104 + 2 * tid]     = v;
            g_at2[q * 104 + 2 * tid + 1] = v;
        }
    } else if (b < 1393) {
        int idx = (b - 1001) * 256 + tid;
        if (idx < 1001 * 100) {
            int q = idx / 100, j = idx % 100;
            float a = b1[j];
            const float* w = W1 + j * 250 + 200;
            const float* e = qet + q * 50;
            for (int k = 0; k < 50; k++) a = fmaf(w[k], e[k], a);
            g_c1[idx] = a;
        }
    } else {
        int i = (b - 1393) * 256 + tid;
        if (i < 5000) {
            g_w2e[i] = W2[i];
        } else if (i < 5400) {
            int idx = i - 5000, c = idx / 100, k = idx % 100;
            float a = 0.f;
            for (int f = 0; f < 50; f++) a = fmaf(Wo[c * 50 + f], W2[f * 100 + k], a);
            g_w2e[i] = a;
        } else if (i < 5500) {
            int k = i - 5400;
            float a = 0.f;
            for (int f = 0; f < 50; f++) a += W2[f * 100 + k];
            g_w2e[i] = a * (1.f / 50.f);
        } else if (i < 5600) {
            g_w2e[i] = 0.f;
        } else if (i < 5656) {
            int j = i - 5600;
            float v = 0.f;
            if (j < 50) v = b2[j];
            else if (j < 54) {
                int c = j - 50;
                v = bo[c];
                for (int f = 0; f < 50; f++) v = fmaf(Wo[c * 50 + f], b2[f], v);
            } else if (j == 54) {
                float a = 0.f;
                for (int f = 0; f < 50; f++) a += b2[f];
                v = a * (1.f / 50.f);
            }
            g_b2e[j] = v;
        }
    }
}

// ================= prepC: erase/add GEMM, ve inline =================
__global__ void prepC(const float* __restrict__ We, const float* __restrict__ be,
                      const float* __restrict__ Wa, const float* __restrict__ ba,
                      const float* __restrict__ Wv, const float* __restrict__ bv) {
    __shared__ float As[16][64];
    __shared__ float Bs[16][64];
    int i0 = blockIdx.x * 64, j0 = blockIdx.y * 64;
    int tid = threadIdx.x;
    int ty = tid >> 4, tx = tid & 15;
    float acc[4][4] = {};
    for (int kb = 0; kb < 200; kb += 16) {
        for (int l = tid; l < 1024; l += 256) {
            {
                int c = l >> 6, r = l & 63;
                int gi = i0 + r, gk = kb + c;
                float val = 0.f;
                if (gi < 4004 && gk < 200) {
                    int q = gi >> 2, rr = gi & 3;
                    val = bv[gk];
                    if (q > 0) {
#pragma unroll
                        for (int cc = 0; cc < 4; cc++) {
                            float w = 1.0f - fabsf((float)(cc - rr)) * (1.0f / 3.0f);
                            if (w > 0.0f)
                                val = fmaf(w, Wv[gk * 4000 + cc * 1000 + q - 1], val);
                        }
                    }
                }
                As[c][r] = val;
            }
            {
                int r = l >> 4, c = l & 15;
                int gj = j0 + r, gk = kb + c;
                float bval = 0.f;
                if (gj < 400 && gk < 200)
                    bval = (gj < 200) ? We[gj * 200 + gk] : Wa[(gj - 200) * 200 + gk];
                Bs[c][r] = bval;
            }
        }
        __syncthreads();
#pragma unroll
        for (int k = 0; k < 16; k++) {
            float a[4], bb[4];
#pragma unroll
            for (int u = 0; u < 4; u++) a[u] = As[k][ty * 4 + u];
#pragma unroll
            for (int u = 0; u < 4; u++) bb[u] = Bs[k][tx * 4 + u];
#pragma unroll
            for (int u = 0; u < 4; u++)
#pragma unroll
                for (int v = 0; v < 4; v++) acc[u][v] = fmaf(a[u], bb[v], acc[u][v]);
        }
        __syncthreads();
    }
#pragma unroll
    for (int u = 0; u < 4; u++) {
        int gi = i0 + ty * 4 + u;
        if (gi >= 4004) break;
#pragma unroll
        for (int v = 0; v < 4; v++) {
            int gj = j0 + tx * 4 + v;
            if (gj >= 400) continue;
            float x = acc[u][v] + ((gj < 200) ? be[gj] : ba[gj - 200]);
            g_ea[(size_t)gi * 400 + gj] = (gj < 200) ? (1.0f / (1.0f + expf(-x))) : tanhf(x);
        }
    }
}

// ================= Phase 1: barrier-free Vm recurrence, G1=4 =================
#define TPB1 416
constexpr int G1 = 4;
// smem: [0,2000) qs int | [2000,4000) rs int | bufs: 13 warps x 2 bufs x 2 slots x 104
constexpr int P1_SMF = 4000 + 13 * 416;   // 9408 floats

__global__ void __launch_bounds__(TPB1, 1)
phase1(const int* __restrict__ questions, const int* __restrict__ responses,
       const float* __restrict__ ivm) {
    __shared__ float sm[P1_SMF];
    int* qs = (int*)sm;
    int* rs = (int*)(sm + 2000);
    const int tid = threadIdx.x;
    const int wid = tid >> 5, lane = tid & 31;
    const int b0 = blockIdx.x * G1;

    for (int i = tid; i < G1 * S_; i += TPB1) {
        qs[i] = questions[b0 * S_ + i];
        rs[i] = responses[b0 * S_ + i];
    }

    const int cp = (tid < 400) ? tid : 399;
    const int g = cp / 100, p = cp % 100;
    const int wg0 = (wid * 32) / 100;
    const int wg1 = min(3, (wid * 32 + 31) / 100);
    const int myslot = (g > wg0) ? 1 : 0;

    ull vm[50];
#pragma unroll
    for (int m = 0; m < 50; m++) vm[m] = *(const ull*)(ivm + m * 200 + 2 * p);

    __syncthreads();   // only block barrier

    float* mybuf = sm + 4000 + wid * 416;   // [buf d][slot s][104]
    const int* qsg = qs + g * S_;
    const int* rsg = rs + g * S_;

    // prologue: attn(0)
    for (int i = lane; i < 52; i += 32) {
        int s = i / 26, j = i % 26;
        int qq = qs[(s ? wg1 : wg0) * S_];
        cp16(mybuf + s * 104 + j * 4, g_at2 + qq * 104 + j * 4);
    }
    asm volatile("cp.async.commit_group;\n" ::: "memory");

    ull eC, aC;
    {
        const float* eb = g_ea + (size_t)(qsg[0] * 4 + rsg[0]) * 400;
        eC = *(const ull*)(eb + 2 * p);
        aC = *(const ull*)(eb + 200 + 2 * p);
    }

    size_t hb = (size_t)(b0 + g) * (S_ * 200) + 2 * p;

    for (int t = 0; t < S_; t++) {
        ull eN = 0ull, aN = 0ull;
        if (t + 1 < S_) {
            const float* eb = g_ea + (size_t)(qsg[t + 1] * 4 + rsg[t + 1]) * 400;
            eN = *(const ull*)(eb + 2 * p);
            aN = *(const ull*)(eb + 200 + 2 * p);
            float* nb = mybuf + ((t + 1) & 1) * 208;
            for (int i = lane; i < 52; i += 32) {
                int s = i / 26, j = i % 26;
                int qq = qs[(s ? wg1 : wg0) * S_ + t + 1];
                cp16(nb + s * 104 + j * 4, g_at2 + qq * 104 + j * 4);
            }
        }
        asm volatile("cp.async.commit_group;\n" ::: "memory");
        asm volatile("cp.async.wait_group 1;\n" ::: "memory");
        __syncwarp();

        const ulonglong2* at2p =
            (const ulonglong2*)(mybuf + (t & 1) * 208 + myslot * 104);
        ull en = eC ^ 0x8000000080000000ULL;
        ull ad = aC;
        ull ra = 0ull, rb = 0ull;
#pragma unroll
        for (int j2 = 0; j2 < 25; j2++) {
            ulonglong2 uu = at2p[j2];
            ull tt;
            FMA2(ra, uu.x, vm[2 * j2], ra);
            FMA2(tt, en, vm[2 * j2], ad);
            FMA2(vm[2 * j2], uu.x, tt, vm[2 * j2]);
            FMA2(rb, uu.y, vm[2 * j2 + 1], rb);
            FMA2(tt, en, vm[2 * j2 + 1], ad);
            FMA2(vm[2 * j2 + 1], uu.y, tt, vm[2 * j2 + 1]);
        }
        ull one2 = PK(1.0f, 1.0f), r2;
        FMA2(r2, rb, one2, ra);
        if (tid < 400)
            *(ull*)(g_h + hb + (size_t)t * 200) = r2;
        eC = eN; aC = aN;
    }
}

// ================= Phase 2: batched MLP, 32 rows/block, 3 blocks/SM ==========
#define TPB2 256
constexpr int R2 = 32;
constexpr int HSTR = 204;
constexpr int H1STR = 102;
constexpr int O2_H   = 0;               // 32 x 204 = 6528
constexpr int O2_H1  = 6528;            // 32 x 102 = 3264
constexpr int O2_W2E = 9792;            // 5600
constexpr int O2_B2E = 15392;           // 56
constexpr int O2_LG  = 15448;           // 128
constexpr int O2_QN  = 15576;           // 32 int
constexpr int P2_SMF = 15608;           // 62,432 B

__global__ void __launch_bounds__(TPB2, 3)
phase2(const int* __restrict__ questions, const float* __restrict__ W1,
       float* __restrict__ outF, float* __restrict__ outM,
       float* __restrict__ outL, float* __restrict__ outP) {
    extern __shared__ float s2[];
    const int tid = threadIdx.x;
    const int n0 = blockIdx.x * R2;
    int* qn = (int*)(s2 + O2_QN);

    // ---- stage A ----
    for (int i = tid; i < 1600; i += TPB2) {
        int r = i / 50, c = i % 50;
        cp16(s2 + O2_H + r * HSTR + c * 4, g_h + (size_t)(n0 + r) * 200 + c * 4);
    }
    for (int i = tid; i < 1400; i += TPB2)
        cp16(s2 + O2_W2E + i * 4, g_w2e + i * 4);
    if (tid < 14) cp16(s2 + O2_B2E + tid * 4, g_b2e + tid * 4);
    if (tid < R2) qn[tid] = questions[n0 + tid];
    asm volatile("cp.async.commit_group;\n" ::: "memory");
    asm volatile("cp.async.wait_group 0;\n" ::: "memory");
    __syncthreads();

    // ---- stage B: h1 = relu(W1[:, :200] @ h + c1[q]), 4j x 4rows ----
    if (tid < 200) {
        int jg = tid / 8, rg = tid % 8;
        int j0 = jg * 4;
        ull acc[4][4] = {};
        for (int k = 0; k < 200; k += 2) {
            ull h[4];
#pragma unroll
            for (int i = 0; i < 4; i++)
                h[i] = *(const ull*)(s2 + O2_H + (rg + 8 * i) * HSTR + k);
#pragma unroll
            for (int j = 0; j < 4; j++) {
                ull w = *(const ull*)(W1 + (j0 + j) * 250 + k);
#pragma unroll
                for (int i = 0; i < 4; i++) FMA2(acc[j][i], w, h[i], acc[j][i]);
            }
        }
#pragma unroll
        for (int j = 0; j < 4; j++)
#pragma unroll
            for (int i = 0; i < 4; i++) {
                int row = rg + 8 * i;
                float v = HADD(acc[j][i]) + g_c1[qn[row] * 100 + j0 + j];
                s2[O2_H1 + row * H1STR + j0 + j] = fmaxf(v, 0.f);
            }
    }
    __syncthreads();

    // ---- stage C: W2e(56x100) @ h1 -> feats+logits+mastery, 4f x 4rows ----
    if (tid < 112) {
        int fg = tid >> 3, rg = tid & 7;    // fg 0..13, rg 0..7
        int f0 = fg * 4;
        ull acc[4][4] = {};
#pragma unroll 5
        for (int kk = 0; kk < 50; kk++) {
            ull h1v[4];
#pragma unroll
            for (int i = 0; i < 4; i++)
                h1v[i] = *(const ull*)(s2 + O2_H1 + (rg + 8 * i) * H1STR + 2 * kk);
#pragma unroll
            for (int j = 0; j < 4; j++) {
                ull w = *(const ull*)(s2 + O2_W2E + (f0 + j) * 100 + 2 * kk);
#pragma unroll
                for (int i = 0; i < 4; i++) FMA2(acc[j][i], w, h1v[i], acc[j][i]);
            }
        }
#pragma unroll
        for (int j = 0; j < 4; j++) {
            int f = f0 + j;
            if (f >= 55) continue;
            float bias = s2[O2_B2E + f];
#pragma unroll
            for (int i = 0; i < 4; i++) {
                int row = rg + 8 * i;
                float val = HADD(acc[j][i]) + bias;
                if (f < 50)      outF[(size_t)(n0 + row) * 50 + f] = val;
                else if (f < 54) s2[O2_LG + row * 4 + (f - 50)] = val;
                else             outM[n0 + row] = val;
            }
        }
    }
    __syncthreads();

    // ---- softmax over logits ----
    if (tid < 128) {
        int row = tid >> 2, c = tid & 3;
        float lg = s2[O2_LG + row * 4 + c];
        float mx = fmaxf(lg, __shfl_xor_sync(0xffffffffu, lg, 1));
        mx = fmaxf(mx, __shfl_xor_sync(0xffffffffu, mx, 2));
        float e = expf(lg - mx);
        float se = e + __shfl_xor_sync(0xffffffffu, e, 1);
        se += __shfl_xor_sync(0xffffffffu, se, 2);
        size_t o = (size_t)(n0 + row) * 4 + c;
        outL[o] = lg;
        outP[o] = e / se;
    }
}

// ---------------------------------------------------------------------------

extern "C" void kernel_launch(void* const* d_in, const int* in_sizes, int n_in,
                              void* d_out, int out_size) {
    const int*   questions = (const int*)d_in[0];
    const int*   responses = (const int*)d_in[1];
    const float* qet       = (const float*)d_in[2];
    const float* Wv        = (const float*)d_in[3];
    const float* bv        = (const float*)d_in[4];
    const float* km        = (const float*)d_in[5];
    const float* ivm       = (const float*)d_in[6];
    const float* Wq        = (const float*)d_in[7];
    const float* bq        = (const float*)d_in[8];
    const float* Wk        = (const float*)d_in[9];
    const float* bk        = (const float*)d_in[10];
    const float* We        = (const float*)d_in[11];
    const float* be        = (const float*)d_in[12];
    const float* Wa        = (const float*)d_in[13];
    const float* ba        = (const float*)d_in[14];
    const float* W1        = (const float*)d_in[15];
    const float* b1        = (const float*)d_in[16];
    const float* W2        = (const float*)d_in[17];
    const float* b2        = (const float*)d_in[18];
    const float* Wo        = (const float*)d_in[19];
    const float* bo        = (const float*)d_in[20];

    float* out  = (float*)d_out;
    float* outF = out;
    float* outM = out + (size_t)512 * 500 * 50;
    float* outL = outM + (size_t)512 * 500;
    float* outP = outL + (size_t)512 * 500 * 4;

    cudaFuncSetAttribute(phase2, cudaFuncAttributeMaxDynamicSharedMemorySize,
                         P2_SMF * 4);

    prepBF<<<1416, 256>>>(qet, Wq, bq, km, Wk, bk, W1, b1, W2, b2, Wo, bo);
    {
        dim3 grid(63, 7);
        prepC<<<grid, 256>>>(We, be, Wa, ba, Wv, bv);
    }
    phase1<<<512 / G1, TPB1>>>(questions, responses, ivm);
    phase2<<<512 * 500 / R2, TPB2, P2_SMF * 4>>>(questions, W1,
                                                 outF, outM, outL, outP);
}

// round 12
// speedup vs baseline: 1.0415x; 1.0415x over previous
#include <cuda_runtime.h>
#include <math.h>

typedef unsigned long long ull;
constexpr int S_ = 500;

// ---------------- device scratch ----------------
__device__ float g_at2[1001 * 104];              // duplicated attn pairs
__device__ float g_c1[1001 * 100];
__device__ float g_ea[(size_t)4004 * 400];
__device__ float g_w2e[56 * 100];                // [W2(50); Wo@W2(4); colmean W2(1); 0]
__device__ float g_b2e[56];
__device__ float g_w1p[100 * 200];               // W1[:, :200] packed (16B-aligned rows)
__device__ float g_h[(size_t)512 * 500 * 200];   // read vectors

// ---------------- f32x2 helpers ----------------
#define FMA2(d, a, b, c) \
    asm("fma.rn.f32x2 %0, %1, %2, %3;" : "=l"(d) : "l"(a), "l"(b), "l"(c))
__device__ __forceinline__ ull PK(float x, float y) {
    ull u;
    asm("mov.b64 %0, {%1, %2};" : "=l"(u) : "r"(__float_as_uint(x)), "r"(__float_as_uint(y)));
    return u;
}
__device__ __forceinline__ float HADD(ull u) {
    unsigned lo, hi;
    asm("mov.b64 {%0, %1}, %2;" : "=r"(lo), "=r"(hi) : "l"(u));
    return __uint_as_float(lo) + __uint_as_float(hi);
}
__device__ __forceinline__ void cp16(float* dst, const float* src) {
    unsigned d = (unsigned)__cvta_generic_to_shared(dst);
    asm volatile("cp.async.ca.shared.global [%0], [%1], 16;\n" :: "r"(d), "l"(src));
}

// ================= prepBF: attn(+tk) | c1 | fold | w1 pack =================
// blocks: [0,1001) attn | [1001,1393) c1 | [1393,1416) fold | [1416,1495) w1p
__global__ void prepBF(const float* __restrict__ qet, const float* __restrict__ Wq,
                       const float* __restrict__ bq,
                       const float* __restrict__ km, const float* __restrict__ Wk,
                       const float* __restrict__ bk,
                       const float* __restrict__ W1, const float* __restrict__ b1,
                       const float* __restrict__ W2, const float* __restrict__ b2,
                       const float* __restrict__ Wo, const float* __restrict__ bo) {
    __shared__ float stk[2500], qe[50], qu[50], lg[50], red[2];
    int b = blockIdx.x, tid = threadIdx.x;
    if (b < 1001) {
        int q = b;
        for (int i = tid; i < 2500; i += 256) {
            int m = i / 50, k = i % 50;
            float a = bk[m];
            for (int l = 0; l < 50; l++) a = fmaf(km[l * 50 + k], Wk[m * 50 + l], a);
            stk[i] = a;
        }
        if (tid < 50) qe[tid] = qet[q * 50 + tid];
        __syncthreads();
        if (tid < 50) {
            float a = bq[tid];
            for (int l = 0; l < 50; l++) a = fmaf(Wq[tid * 50 + l], qe[l], a);
            qu[tid] = tanhf(a);
        }
        __syncthreads();
        if (tid < 50) {
            float a = 0.f;
            for (int k = 0; k < 50; k++) a = fmaf(stk[tid * 50 + k], qu[k], a);
            lg[tid] = a;
        }
        __syncthreads();
        if (tid == 0) {
            float mx = -1e30f;
            for (int m = 0; m < 50; m++) mx = fmaxf(mx, lg[m]);
            float s = 0.f;
            for (int m = 0; m < 50; m++) s += expf(lg[m] - mx);
            red[0] = mx; red[1] = 1.f / s;
        }
        __syncthreads();
        if (tid < 52) {
            float v = (tid < 50) ? expf(lg[tid] - red[0]) * red[1] : 0.f;
            g_at2[q * 104 + 2 * tid]     = v;
            g_at2[q * 104 + 2 * tid + 1] = v;
        }
    } else if (b < 1393) {
        int idx = (b - 1001) * 256 + tid;
        if (idx < 1001 * 100) {
            int q = idx / 100, j = idx % 100;
            float a = b1[j];
            const float* w = W1 + j * 250 + 200;
            const float* e = qet + q * 50;
            for (int k = 0; k < 50; k++) a = fmaf(w[k], e[k], a);
            g_c1[idx] = a;
        }
    } else if (b < 1416) {
        int i = (b - 1393) * 256 + tid;
        if (i < 5000) {
            g_w2e[i] = W2[i];
        } else if (i < 5400) {
            int idx = i - 5000, c = idx / 100, k = idx % 100;
            float a = 0.f;
            for (int f = 0; f < 50; f++) a = fmaf(Wo[c * 50 + f], W2[f * 100 + k], a);
            g_w2e[i] = a;
        } else if (i < 5500) {
            int k = i - 5400;
            float a = 0.f;
            for (int f = 0; f < 50; f++) a += W2[f * 100 + k];
            g_w2e[i] = a * (1.f / 50.f);
        } else if (i < 5600) {
            g_w2e[i] = 0.f;
        } else if (i < 5656) {
            int j = i - 5600;
            float v = 0.f;
            if (j < 50) v = b2[j];
            else if (j < 54) {
                int c = j - 50;
                v = bo[c];
                for (int f = 0; f < 50; f++) v = fmaf(Wo[c * 50 + f], b2[f], v);
            } else if (j == 54) {
                float a = 0.f;
                for (int f = 0; f < 50; f++) a += b2[f];
                v = a * (1.f / 50.f);
            }
            g_b2e[j] = v;
        }
    } else {
        int i = (b - 1416) * 256 + tid;
        if (i < 100 * 200) {
            int r = i / 200, c = i % 200;
            g_w1p[i] = W1[r * 250 + c];
        }
    }
}

// ================= prepC: erase/add GEMM, ve inline =================
__global__ void prepC(const float* __restrict__ We, const float* __restrict__ be,
                      const float* __restrict__ Wa, const float* __restrict__ ba,
                      const float* __restrict__ Wv, const float* __restrict__ bv) {
    __shared__ float As[16][64];
    __shared__ float Bs[16][64];
    int i0 = blockIdx.x * 64, j0 = blockIdx.y * 64;
    int tid = threadIdx.x;
    int ty = tid >> 4, tx = tid & 15;
    float acc[4][4] = {};
    for (int kb = 0; kb < 200; kb += 16) {
        for (int l = tid; l < 1024; l += 256) {
            {
                int c = l >> 6, r = l & 63;
                int gi = i0 + r, gk = kb + c;
                float val = 0.f;
                if (gi < 4004 && gk < 200) {
                    int q = gi >> 2, rr = gi & 3;
                    val = bv[gk];
                    if (q > 0) {
#pragma unroll
                        for (int cc = 0; cc < 4; cc++) {
                            float w = 1.0f - fabsf((float)(cc - rr)) * (1.0f / 3.0f);
                            if (w > 0.0f)
                                val = fmaf(w, Wv[gk * 4000 + cc * 1000 + q - 1], val);
                        }
                    }
                }
                As[c][r] = val;
            }
            {
                int r = l >> 4, c = l & 15;
                int gj = j0 + r, gk = kb + c;
                float bval = 0.f;
                if (gj < 400 && gk < 200)
                    bval = (gj < 200) ? We[gj * 200 + gk] : Wa[(gj - 200) * 200 + gk];
                Bs[c][r] = bval;
            }
        }
        __syncthreads();
#pragma unroll
        for (int k = 0; k < 16; k++) {
            float a[4], bb[4];
#pragma unroll
            for (int u = 0; u < 4; u++) a[u] = As[k][ty * 4 + u];
#pragma unroll
            for (int u = 0; u < 4; u++) bb[u] = Bs[k][tx * 4 + u];
#pragma unroll
            for (int u = 0; u < 4; u++)
#pragma unroll
                for (int v = 0; v < 4; v++) acc[u][v] = fmaf(a[u], bb[v], acc[u][v]);
        }
        __syncthreads();
    }
#pragma unroll
    for (int u = 0; u < 4; u++) {
        int gi = i0 + ty * 4 + u;
        if (gi >= 4004) break;
#pragma unroll
        for (int v = 0; v < 4; v++) {
            int gj = j0 + tx * 4 + v;
            if (gj >= 400) continue;
            float x = acc[u][v] + ((gj < 200) ? be[gj] : ba[gj - 200]);
            g_ea[(size_t)gi * 400 + gj] = (gj < 200) ? (1.0f / (1.0f + expf(-x))) : tanhf(x);
        }
    }
}

// ================= Phase 1: barrier-free Vm recurrence, G1=4 =================
#define TPB1 416
constexpr int G1 = 4;
constexpr int P1_SMF = 4000 + 13 * 416;

__global__ void __launch_bounds__(TPB1, 1)
phase1(const int* __restrict__ questions, const int* __restrict__ responses,
       const float* __restrict__ ivm) {
    __shared__ float sm[P1_SMF];
    int* qs = (int*)sm;
    int* rs = (int*)(sm + 2000);
    const int tid = threadIdx.x;
    const int wid = tid >> 5, lane = tid & 31;
    const int b0 = blockIdx.x * G1;

    for (int i = tid; i < G1 * S_; i += TPB1) {
        qs[i] = questions[b0 * S_ + i];
        rs[i] = responses[b0 * S_ + i];
    }

    const int cp = (tid < 400) ? tid : 399;
    const int g = cp / 100, p = cp % 100;
    const int wg0 = (wid * 32) / 100;
    const int wg1 = min(3, (wid * 32 + 31) / 100);
    const int myslot = (g > wg0) ? 1 : 0;

    ull vm[50];
#pragma unroll
    for (int m = 0; m < 50; m++) vm[m] = *(const ull*)(ivm + m * 200 + 2 * p);

    __syncthreads();

    float* mybuf = sm + 4000 + wid * 416;
    const int* qsg = qs + g * S_;
    const int* rsg = rs + g * S_;

    for (int i = lane; i < 52; i += 32) {
        int s = i / 26, j = i % 26;
        int qq = qs[(s ? wg1 : wg0) * S_];
        cp16(mybuf + s * 104 + j * 4, g_at2 + qq * 104 + j * 4);
    }
    asm volatile("cp.async.commit_group;\n" ::: "memory");

    ull eC, aC;
    {
        const float* eb = g_ea + (size_t)(qsg[0] * 4 + rsg[0]) * 400;
        eC = *(const ull*)(eb + 2 * p);
        aC = *(const ull*)(eb + 200 + 2 * p);
    }

    size_t hb = (size_t)(b0 + g) * (S_ * 200) + 2 * p;

    for (int t = 0; t < S_; t++) {
        ull eN = 0ull, aN = 0ull;
        if (t + 1 < S_) {
            const float* eb = g_ea + (size_t)(qsg[t + 1] * 4 + rsg[t + 1]) * 400;
            eN = *(const ull*)(eb + 2 * p);
            aN = *(const ull*)(eb + 200 + 2 * p);
            float* nb = mybuf + ((t + 1) & 1) * 208;
            for (int i = lane; i < 52; i += 32) {
                int s = i / 26, j = i % 26;
                int qq = qs[(s ? wg1 : wg0) * S_ + t + 1];
                cp16(nb + s * 104 + j * 4, g_at2 + qq * 104 + j * 4);
            }
        }
        asm volatile("cp.async.commit_group;\n" ::: "memory");
        asm volatile("cp.async.wait_group 1;\n" ::: "memory");
        __syncwarp();

        const ulonglong2* at2p =
            (const ulonglong2*)(mybuf + (t & 1) * 208 + myslot * 104);
        ull en = eC ^ 0x8000000080000000ULL;
        ull ad = aC;
        ull ra = 0ull, rb = 0ull;
#pragma unroll
        for (int j2 = 0; j2 < 25; j2++) {
            ulonglong2 uu = at2p[j2];
            ull tt;
            FMA2(ra, uu.x, vm[2 * j2], ra);
            FMA2(tt, en, vm[2 * j2], ad);
            FMA2(vm[2 * j2], uu.x, tt, vm[2 * j2]);
            FMA2(rb, uu.y, vm[2 * j2 + 1], rb);
            FMA2(tt, en, vm[2 * j2 + 1], ad);
            FMA2(vm[2 * j2 + 1], uu.y, tt, vm[2 * j2 + 1]);
        }
        ull one2 = PK(1.0f, 1.0f), r2;
        FMA2(r2, rb, one2, ra);
        if (tid < 400)
            *(ull*)(g_h + hb + (size_t)t * 200) = r2;
        eC = eN; aC = aN;
    }
}

// ================= Phase 2: batched MLP, 64 rows/block, wide loads ===========
#define TPB2 256
constexpr int R2 = 64;
constexpr int HSTR = 204;     // conflict-free for 8-row ulonglong2 (12-bank step)
constexpr int H1STR = 108;    // conflict-free + 16B-aligned rows
constexpr int O2_H   = 0;               // 64 x 204 = 13056
constexpr int O2_H1  = 13056;           // 64 x 108 = 6912
constexpr int O2_W2E = 19968;           // 5600
constexpr int O2_B2E = 25568;           // 56
constexpr int O2_LG  = 25624;           // 256
constexpr int O2_QN  = 25880;           // 64 int
constexpr int P2_SMF = 25944;           // 103,776 B

__global__ void __launch_bounds__(TPB2, 2)
phase2(const int* __restrict__ questions,
       float* __restrict__ outF, float* __restrict__ outM,
       float* __restrict__ outL, float* __restrict__ outP) {
    extern __shared__ float s2[];
    const int tid = threadIdx.x;
    const int n0 = blockIdx.x * R2;
    int* qn = (int*)(s2 + O2_QN);

    // ---- stage A ----
    for (int i = tid; i < 3200; i += TPB2) {
        int r = i / 50, c = i % 50;
        cp16(s2 + O2_H + r * HSTR + c * 4, g_h + (size_t)(n0 + r) * 200 + c * 4);
    }
    for (int i = tid; i < 1400; i += TPB2)
        cp16(s2 + O2_W2E + i * 4, g_w2e + i * 4);
    if (tid < 14) cp16(s2 + O2_B2E + tid * 4, g_b2e + tid * 4);
    if (tid < R2) qn[tid] = questions[n0 + tid];
    asm volatile("cp.async.commit_group;\n" ::: "memory");
    asm volatile("cp.async.wait_group 0;\n" ::: "memory");
    __syncthreads();

    // ---- stage B: h1 = relu(W1p @ h + c1[q]), 4j x 8rows, 128-bit loads ----
    if (tid < 200) {
        int jg = tid / 8, rg = tid % 8;
        int j0 = jg * 4;
        ull acc[4][8] = {};
        for (int k = 0; k < 200; k += 4) {
            ulonglong2 h[8];
#pragma unroll
            for (int i = 0; i < 8; i++)
                h[i] = *(const ulonglong2*)(s2 + O2_H + (rg + 8 * i) * HSTR + k);
#pragma unroll
            for (int j = 0; j < 4; j++) {
                ulonglong2 w = *(const ulonglong2*)(g_w1p + (j0 + j) * 200 + k);
#pragma unroll
                for (int i = 0; i < 8; i++) {
                    FMA2(acc[j][i], w.x, h[i].x, acc[j][i]);
                    FMA2(acc[j][i], w.y, h[i].y, acc[j][i]);
                }
            }
        }
#pragma unroll
        for (int j = 0; j < 4; j++)
#pragma unroll
            for (int i = 0; i < 8; i++) {
                int row = rg + 8 * i;
                float v = HADD(acc[j][i]) + g_c1[qn[row] * 100 + j0 + j];
                s2[O2_H1 + row * H1STR + j0 + j] = fmaxf(v, 0.f);
            }
    }
    __syncthreads();

    // ---- stage C: W2e(56x100) @ h1, 2f x 8rows, h1 via LDS.128 ----
    if (tid < 224) {
        int fg = tid >> 3, rg = tid & 7;    // fg 0..27, f0 = fg*2
        int f0 = fg * 2;
        ull acc[2][8] = {};
        for (int k = 0; k < 100; k += 4) {
            ulonglong2 h1v[8];
#pragma unroll
            for (int i = 0; i < 8; i++)
                h1v[i] = *(const ulonglong2*)(s2 + O2_H1 + (rg + 8 * i) * H1STR + k);
#pragma unroll
            for (int j = 0; j < 2; j++) {
                ull w0 = *(const ull*)(s2 + O2_W2E + (f0 + j) * 100 + k);
                ull w1 = *(const ull*)(s2 + O2_W2E + (f0 + j) * 100 + k + 2);
#pragma unroll
                for (int i = 0; i < 8; i++) {
                    FMA2(acc[j][i], w0, h1v[i].x, acc[j][i]);
                    FMA2(acc[j][i], w1, h1v[i].y, acc[j][i]);
                }
            }
        }
#pragma unroll
        for (int j = 0; j < 2; j++) {
            int f = f0 + j;
            if (f >= 55) continue;
            float bias = s2[O2_B2E + f];
#pragma unroll
            for (int i = 0; i < 8; i++) {
                int row = rg + 8 * i;
                float val = HADD(acc[j][i]) + bias;
                if (f < 50)      outF[(size_t)(n0 + row) * 50 + f] = val;
                else if (f < 54) s2[O2_LG + row * 4 + (f - 50)] = val;
                else             outM[n0 + row] = val;
            }
        }
    }
    __syncthreads();

    // ---- softmax over logits (all 256 threads = 64 rows x 4) ----
    {
        int row = tid >> 2, c = tid & 3;
        float lg = s2[O2_LG + row * 4 + c];
        float mx = fmaxf(lg, __shfl_xor_sync(0xffffffffu, lg, 1));
        mx = fmaxf(mx, __shfl_xor_sync(0xffffffffu, mx, 2));
        float e = expf(lg - mx);
        float se = e + __shfl_xor_sync(0xffffffffu, e, 1);
        se += __shfl_xor_sync(0xffffffffu, se, 2);
        size_t o = (size_t)(n0 + row) * 4 + c;
        outL[o] = lg;
        outP[o] = e / se;
    }
}

// ---------------------------------------------------------------------------

extern "C" void kernel_launch(void* const* d_in, const int* in_sizes, int n_in,
                              void* d_out, int out_size) {
    const int*   questions = (const int*)d_in[0];
    const int*   responses = (const int*)d_in[1];
    const float* qet       = (const float*)d_in[2];
    const float* Wv        = (const float*)d_in[3];
    const float* bv        = (const float*)d_in[4];
    const float* km        = (const float*)d_in[5];
    const float* ivm       = (const float*)d_in[6];
    const float* Wq        = (const float*)d_in[7];
    const float* bq        = (const float*)d_in[8];
    const float* Wk        = (const float*)d_in[9];
    const float* bk        = (const float*)d_in[10];
    const float* We        = (const float*)d_in[11];
    const float* be        = (const float*)d_in[12];
    const float* Wa        = (const float*)d_in[13];
    const float* ba        = (const float*)d_in[14];
    const float* W1        = (const float*)d_in[15];
    const float* b1        = (const float*)d_in[16];
    const float* W2        = (const float*)d_in[17];
    const float* b2        = (const float*)d_in[18];
    const float* Wo        = (const float*)d_in[19];
    const float* bo        = (const float*)d_in[20];

    float* out  = (float*)d_out;
    float* outF = out;
    float* outM = out + (size_t)512 * 500 * 50;
    float* outL = outM + (size_t)512 * 500;
    float* outP = outL + (size_t)512 * 500 * 4;

    cudaFuncSetAttribute(phase2, cudaFuncAttributeMaxDynamicSharedMemorySize,
                         P2_SMF * 4);

    prepBF<<<1495, 256>>>(qet, Wq, bq, km, Wk, bk, W1, b1, W2, b2, Wo, bo);
    {
        dim3 grid(63, 7);
        prepC<<<grid, 256>>>(We, be, Wa, ba, Wv, bv);
    }
    phase1<<<512 / G1, TPB1>>>(questions, responses, ivm);
    phase2<<<512 * 500 / R2, TPB2, P2_SMF * 4>>>(questions,
                                                 outF, outM, outL, outP);
}